// round 15
// baseline (speedup 1.0000x reference)
#include <cuda_runtime.h>
#include <math.h>

// ---------------- problem dims ----------------
#define PXTOT 32768            // B*H*W = 8*64*64
#define NY    2097152          // PXTOT * 64
#define NH    4194304          // PXTOT * 128
#define NV4   (NY/4)
#define NITERS 32
#define NTHR  512
#define NPHASE 224             // max evals = 1 + 32*6 = 193

// ---------------- device state ----------------
__device__ float g_buf0[NY];       // y / ytmp ping-pong
__device__ float g_buf1[NY];
__device__ float g_k[7][NY];
__device__ float g_h1[NH];
__device__ double g_sumsq[NITERS];
__device__ unsigned int g_bar;
__device__ unsigned int g_tks[NPHASE];  // per-phase ticket counters
__device__ unsigned int g_f1[256];   // conv1 tile completion (eval number)
__device__ unsigned int g_f2[256];   // conv23 tile completion (eval number)

// ---------------- smem layout (floats) for the fused conv2+conv3 phase ------
// in_s DUP-transposed: [4 ri][16 cc][136]  (each px stored as (v,v) pair)
#define S_IN  0                // 4*16*136     = 8704
#define S_W2  8704             // [9][16][128] = 18432
#define S_WT  27136            // [9][128]     = 1152
#define S_H2  28288            // [128][136]   = 17408
#define S_W3  45696            // [129][64]    = 8256
#define S_TOT 53952            // * 4 B = 215808 B

// ---------------- f32x2 helpers ----------------
__device__ __forceinline__ unsigned long long pk2(float lo, float hi) {
  unsigned long long r;
  asm("mov.b64 %0, {%1, %2};" : "=l"(r) : "f"(lo), "f"(hi));
  return r;
}
__device__ __forceinline__ unsigned long long dup2(float a) { return pk2(a, a); }
__device__ __forceinline__ unsigned long long fma2(unsigned long long a,
                                                   unsigned long long b,
                                                   unsigned long long c) {
  unsigned long long d;
  asm("fma.rn.f32x2 %0, %1, %2, %3;" : "=l"(d) : "l"(a), "l"(b), "l"(c));
  return d;
}
__device__ __forceinline__ void upk2(float& lo, float& hi, unsigned long long v) {
  asm("mov.b64 {%0, %1}, %2;" : "=f"(lo), "=f"(hi) : "l"(v));
}

// ---------------- init node ----------------
__global__ void init_k() {
  g_bar = 0u;
  for (int i = 0; i < NPHASE; i++) g_tks[i] = 0u;
  for (int i = 0; i < NITERS; i++) g_sumsq[i] = 0.0;
  for (int i = 0; i < 256; i++) { g_f1[i] = 0u; g_f2[i] = 0u; }
}

// ---------------- software grid barrier ----------------
__device__ __forceinline__ void gsync(unsigned int& bt, unsigned int nb) {
  __syncthreads();
  if (threadIdx.x == 0) {
    __threadfence();
    atomicAdd(&g_bar, 1u);
    bt += nb;
    while ((int)(*(volatile unsigned int*)&g_bar - bt) < 0) __nanosleep(32);
    __threadfence();
  }
  __syncthreads();
}

// ---------------- per-phase tile tickets ----------------
__device__ __forceinline__ int grab(unsigned int* ctr, int nt, int* s_t) {
  if (threadIdx.x == 0) {
    unsigned int tk = atomicAdd(ctr, 1u);
    int loc = (int)tk;
    *s_t = (loc >= 0 && loc < nt) ? loc : -1;
  }
  __syncthreads();
  int r = *s_t;
  __syncthreads();
  return r;
}

// ---------------- dataflow flags ----------------
__device__ __forceinline__ void waitflags(unsigned int* f, int b, int plo, int phi,
                                          unsigned int thr) {
  if (threadIdx.x == 0) {
    for (int q = plo; q <= phi; q++) {
      volatile unsigned int* p = f + b * 32 + q;
      while (*p < thr) __nanosleep(20);
    }
    __threadfence();
  }
  __syncthreads();
}
__device__ __forceinline__ void setflag(unsigned int* f, int idx, unsigned int v) {
  __syncthreads();
  if (threadIdx.x == 0) {
    __threadfence();
    *(volatile unsigned int*)(f + idx) = v;
  }
}

// ---------------- fused f-eval: one ticket stream, flag-synced ----------------
// tickets 0..255: conv1 tiles (128 px = 2 rows), 256..511: conv23 tiles (same idx).
__device__ void feval_phase(
    float tval,
    const float* __restrict__ in,                     // conv1 source
    const float* __restrict__ kcmb, float ccmb, int do_cmb,  // inline FSAL combine
    const float* __restrict__ w1, const float* __restrict__ b1,
    const float* __restrict__ w2, const float* __restrict__ b2,
    const float* __restrict__ w3, const float* __restrict__ b3,
    int kout, int mode,
    const float* kl0, const float* kl1, const float* kl2, const float* kl3,
    float cl0, float cl1, float cl2, float cl3, int nload, float cacc,
    const float* __restrict__ y, float* __restrict__ yt,
    float hs, int it,
    float* s, double* s_red, unsigned int ev,
    unsigned int nb, int* s_t) {
  const int tid = threadIdx.x;
  const float4* w14 = (const float4*)w1;
  const float4* w24 = (const float4*)w2;
  const float4* w34 = (const float4*)w3;
  const float4* in4c1 = (const float4*)in;
  const float4* kc4 = (const float4*)kcmb;
  const float4* h14 = (const float4*)g_h1;
  const float2* y2  = (const float2*)y;
  float2* yt2 = (float2*)yt;
  const float2* p0 = (const float2*)kl0;
  const float2* p1 = (const float2*)kl1;
  const float2* p2 = (const float2*)kl2;
  const float2* p3 = (const float2*)kl3;
  const unsigned long long td = dup2(tval);
  double local = 0.0;

  while (true) {
    int tk = grab(&g_tks[ev], 512, s_t);
    if (tk < 0) break;

    if (tk < 256) {
      // ================= conv1 tile =================
      const int j = tk, jb = j >> 5, jp = j & 31;
      waitflags(g_f2, jb, jp > 0 ? jp - 1 : 0, jp < 31 ? jp + 1 : 31, ev - 1);
      float* in_s = s;                 // [32 ch][264]  (dup pairs)
      float* w_s  = s + 8448;          // [32 ch][128 f]
      const int f0  = (tid & 31) * 4;
      const int px0 = (tid >> 5) * 8;
      const int pxbase = j * 128;
      unsigned long long acc[8][2];
      {
        unsigned long long bp0 = pk2(b1[f0]   + tval * w1[f0],
                                     b1[f0+1] + tval * w1[f0+1]);
        unsigned long long bp1 = pk2(b1[f0+2] + tval * w1[f0+2],
                                     b1[f0+3] + tval * w1[f0+3]);
#pragma unroll
        for (int i = 0; i < 8; i++) { acc[i][0] = bp0; acc[i][1] = bp1; }
      }
      for (int ch = 0; ch < 64; ch += 32) {
        __syncthreads();
#pragma unroll
        for (int l = 0; l < 2; l++) {
          int idx = tid + l * NTHR;
          int px = idx >> 3, c4 = idx & 7;
          size_t goff = (size_t)(pxbase + px) * 16 + (ch >> 2) + c4;
          float4 v = in4c1[goff];
          if (do_cmb) {      // v = y + hs*(ccmb*k1)  (two-op rounding = epilogue)
            float4 kv = kc4[goff];
            v.x = fmaf(hs, ccmb * kv.x, v.x);
            v.y = fmaf(hs, ccmb * kv.y, v.y);
            v.z = fmaf(hs, ccmb * kv.z, v.z);
            v.w = fmaf(hs, ccmb * kv.w, v.w);
          }
          float* bp = &in_s[(c4 * 4) * 264 + px * 2];
          *(float2*)&bp[0]   = make_float2(v.x, v.x);
          *(float2*)&bp[264] = make_float2(v.y, v.y);
          *(float2*)&bp[528] = make_float2(v.z, v.z);
          *(float2*)&bp[792] = make_float2(v.w, v.w);
        }
#pragma unroll
        for (int l = 0; l < 2; l++) {
          int idx = tid + l * NTHR;
          int k = idx >> 5, f4 = idx & 31;
          ((float4*)w_s)[k * 32 + f4] = w14[(size_t)(1 + ch + k) * 32 + f4];
        }
        __syncthreads();
#pragma unroll 4
        for (int k = 0; k < 32; k++) {
          ulonglong2 wA = *(const ulonglong2*)&w_s[k*128 + f0];
          const float* ab = &in_s[k*264 + px0*2];
          ulonglong2 A0 = *(const ulonglong2*)&ab[0];   // dup(px0), dup(px0+1)
          ulonglong2 A1 = *(const ulonglong2*)&ab[4];
          ulonglong2 A2 = *(const ulonglong2*)&ab[8];
          ulonglong2 A3 = *(const ulonglong2*)&ab[12];
          acc[0][0] = fma2(A0.x, wA.x, acc[0][0]); acc[0][1] = fma2(A0.x, wA.y, acc[0][1]);
          acc[1][0] = fma2(A0.y, wA.x, acc[1][0]); acc[1][1] = fma2(A0.y, wA.y, acc[1][1]);
          acc[2][0] = fma2(A1.x, wA.x, acc[2][0]); acc[2][1] = fma2(A1.x, wA.y, acc[2][1]);
          acc[3][0] = fma2(A1.y, wA.x, acc[3][0]); acc[3][1] = fma2(A1.y, wA.y, acc[3][1]);
          acc[4][0] = fma2(A2.x, wA.x, acc[4][0]); acc[4][1] = fma2(A2.x, wA.y, acc[4][1]);
          acc[5][0] = fma2(A2.y, wA.x, acc[5][0]); acc[5][1] = fma2(A2.y, wA.y, acc[5][1]);
          acc[6][0] = fma2(A3.x, wA.x, acc[6][0]); acc[6][1] = fma2(A3.x, wA.y, acc[6][1]);
          acc[7][0] = fma2(A3.y, wA.x, acc[7][0]); acc[7][1] = fma2(A3.y, wA.y, acc[7][1]);
        }
      }
      float4* out4 = (float4*)g_h1;
#pragma unroll
      for (int i = 0; i < 8; i++) {
        float o[4];
        upk2(o[0], o[1], acc[i][0]); upk2(o[2], o[3], acc[i][1]);
#pragma unroll
        for (int jj = 0; jj < 4; jj++) o[jj] = fmaxf(o[jj], 0.f);
        out4[(size_t)(pxbase + px0 + i) * 32 + (f0 >> 2)] =
            make_float4(o[0], o[1], o[2], o[3]);
      }
      setflag(g_f1, j, ev);

    } else {
      // ================= conv23 tile =================
      const int blk = tk - 256;
      const int b   = blk >> 5;
      const int p   = blk & 31;
      const int oy0 = p * 2;
      waitflags(g_f1, b, p > 0 ? p - 1 : 0, p < 31 ? p + 1 : 31, ev);
      const int f0   = (tid & 31) * 4;
      const int px0  = (tid >> 5) * 4;
      const int f0c  = (tid & 31) * 2;
      const int px0c = (tid >> 5) * 8;
      // one-time per tile: w3, wt, halo zeros
#pragma unroll
      for (int l = 0; l < 5; l++) {
        int idx = tid + l * NTHR;
        if (idx < 2064) ((float4*)(s + S_W3))[idx] = w34[idx];
      }
      if (tid < 288) {
        int tap = tid >> 5, f4 = tid & 31;
        ((float4*)(s + S_WT))[tap * 32 + f4] = w24[(size_t)tap * 129 * 32 + f4];
      }
      if (tid >= 384 && tid < 512) {   // zero halo px pairs (px 0 and 65)
        int z = tid - 384;
        int ri = z >> 5, cc = (z >> 1) & 15, col = (z & 1) * 65;
        *(float2*)&s[S_IN + (ri * 16 + cc) * 136 + col * 2] = make_float2(0.f, 0.f);
      }
      unsigned long long acc[2][4][2];
      {
        unsigned long long bp0 = pk2(b2[f0], b2[f0+1]);
        unsigned long long bp1 = pk2(b2[f0+2], b2[f0+3]);
#pragma unroll
        for (int r = 0; r < 2; r++)
#pragma unroll
          for (int i = 0; i < 4; i++) { acc[r][i][0] = bp0; acc[r][i][1] = bp1; }
      }
      __syncthreads();
      // time-channel contribution with border-valid tap masking
#pragma unroll
      for (int ky = 0; ky < 3; ky++) {
#pragma unroll
        for (int kx = 0; kx < 3; kx++) {
          ulonglong2 wp = *(const ulonglong2*)&s[S_WT + (ky * 3 + kx) * 128 + f0];
#pragma unroll
          for (int r = 0; r < 2; r++) {
            int grow = oy0 + r + ky - 1;
            if (grow >= 0 && grow < 64) {
#pragma unroll
              for (int i = 0; i < 4; i++) {
                int col = px0 + i + kx - 1;
                if (col >= 0 && col < 64) {
                  acc[r][i][0] = fma2(td, wp.x, acc[r][i][0]);
                  acc[r][i][1] = fma2(td, wp.y, acc[r][i][1]);
                }
              }
            }
          }
        }
      }
      // stage A: conv2 over 8 chunks of 16 input channels
      for (int ch = 0; ch < 128; ch += 16) {
        __syncthreads();
        // input: 4 rows x 64 px x 16 ch; DUP-transposed [ri][cc][136]
#pragma unroll
        for (int l = 0; l < 2; l++) {
          int idx = tid + l * NTHR;
          int ri = idx >> 8, px = (idx & 255) >> 2, q = idx & 3;
          int row = oy0 + ri - 1;
          float4 v = make_float4(0.f, 0.f, 0.f, 0.f);
          if (row >= 0 && row < 64)
            v = h14[((size_t)((b * 64 + row) * 64 + px)) * 32 + (ch >> 2) + q];
          float* bp = &s[S_IN + (ri * 16 + q * 4) * 136 + (px + 1) * 2];
          *(float2*)&bp[0]   = make_float2(v.x, v.x);
          *(float2*)&bp[136] = make_float2(v.y, v.y);
          *(float2*)&bp[272] = make_float2(v.z, v.z);
          *(float2*)&bp[408] = make_float2(v.w, v.w);
        }
#pragma unroll
        for (int l = 0; l < 9; l++) {
          int idx = tid + l * NTHR;
          int tap = idx >> 9, rem = idx & 511, cc = rem >> 5, f4 = rem & 31;
          ((float4*)(s + S_W2))[(tap * 16 + cc) * 32 + f4] =
              w24[((size_t)tap * 129 + 1 + ch + cc) * 32 + f4];
        }
        __syncthreads();
        for (int cc = 0; cc < 16; cc++) {
          unsigned long long dv[4][6];
#pragma unroll
          for (int ri = 0; ri < 4; ri++) {
            const float* bp = &s[S_IN + (ri * 16 + cc) * 136 + px0 * 2];
            ulonglong2 D0 = *(const ulonglong2*)&bp[0];
            ulonglong2 D1 = *(const ulonglong2*)&bp[4];
            ulonglong2 D2 = *(const ulonglong2*)&bp[8];
            dv[ri][0] = D0.x; dv[ri][1] = D0.y;
            dv[ri][2] = D1.x; dv[ri][3] = D1.y;
            dv[ri][4] = D2.x; dv[ri][5] = D2.y;
          }
#pragma unroll
          for (int ky = 0; ky < 3; ky++) {
#pragma unroll
            for (int kx = 0; kx < 3; kx++) {
              ulonglong2 wv =
                  *(const ulonglong2*)&s[S_W2 + ((ky * 3 + kx) * 16 + cc) * 128 + f0];
#pragma unroll
              for (int r = 0; r < 2; r++) {
#pragma unroll
                for (int i = 0; i < 4; i++) {
                  unsigned long long a = dv[r + ky][i + kx];
                  acc[r][i][0] = fma2(a, wv.x, acc[r][i][0]);
                  acc[r][i][1] = fma2(a, wv.y, acc[r][i][1]);
                }
              }
            }
          }
        }
      }
      // stage A epilogue: relu + h2 tile to smem [px][136]
#pragma unroll
      for (int r = 0; r < 2; r++) {
#pragma unroll
        for (int i = 0; i < 4; i++) {
          int p_t = r * 64 + px0 + i;
#pragma unroll
          for (int jj = 0; jj < 2; jj++) {
            float lo, hi;
            upk2(lo, hi, acc[r][i][jj]);
            *(float2*)&s[S_H2 + p_t * 136 + f0 + 2*jj] =
                make_float2(fmaxf(lo, 0.f), fmaxf(hi, 0.f));
          }
        }
      }
      __syncthreads();
      // stage B: conv3 on the smem tile (k blocked by 4, vector a loads)
      unsigned long long accB[8];
      {
        unsigned long long bp = pk2(b3[f0c]   + tval * w3[f0c],
                                    b3[f0c+1] + tval * w3[f0c+1]);
#pragma unroll
        for (int i = 0; i < 8; i++) accB[i] = bp;
      }
#pragma unroll 2
      for (int k0 = 0; k0 < 128; k0 += 4) {
        float4 av[8];
#pragma unroll
        for (int i = 0; i < 8; i++)
          av[i] = *(const float4*)&s[S_H2 + (px0c + i) * 136 + k0];
#pragma unroll
        for (int kk = 0; kk < 4; kk++) {
          unsigned long long wv =
              *(const unsigned long long*)&s[S_W3 + (1 + k0 + kk) * 64 + f0c];
#pragma unroll
          for (int i = 0; i < 8; i++)
            accB[i] = fma2(dup2(((const float*)&av[i])[kk]), wv, accB[i]);
        }
      }
      // fused dopri5 epilogue (float2 granularity)
      const size_t pxg0 = (size_t)(b * 64 + oy0) * 64;
      float2* out2 = (float2*)&g_k[kout][0];
      if (mode == 0) {
#pragma unroll
        for (int i = 0; i < 8; i++) {
          size_t off = (pxg0 + px0c + i) * 32 + (f0c >> 1);
          float klo, khi;
          upk2(klo, khi, accB[i]);
          out2[off] = make_float2(klo, khi);
          float sx = 0.f, sy = 0.f;
          if (nload > 0) { float2 v = p0[off]; sx = fmaf(cl0,v.x,sx); sy = fmaf(cl0,v.y,sy); }
          if (nload > 1) { float2 v = p1[off]; sx = fmaf(cl1,v.x,sx); sy = fmaf(cl1,v.y,sy); }
          if (nload > 2) { float2 v = p2[off]; sx = fmaf(cl2,v.x,sx); sy = fmaf(cl2,v.y,sy); }
          if (nload > 3) { float2 v = p3[off]; sx = fmaf(cl3,v.x,sx); sy = fmaf(cl3,v.y,sy); }
          sx = fmaf(cacc, klo, sx); sy = fmaf(cacc, khi, sy);
          float2 yv = y2[off];
          yt2[off] = make_float2(fmaf(hs,sx,yv.x), fmaf(hs,sy,yv.y));
        }
      } else {
        const float E1f = (float)( 71.0 / 57600.0);
        const float E3f = (float)(-71.0 / 16695.0);
        const float E4f = (float)( 71.0 / 1920.0);
        const float E5f = (float)(-17253.0 / 339200.0);
        const float E6f = (float)( 22.0 / 525.0);
        const float E7f = (float)(-1.0 / 40.0);
        const float2* q1 = p0;                      // k1 buffer (FSAL-indexed)
        const float2* q3 = (const float2*)g_k[2];
        const float2* q4 = (const float2*)g_k[3];
        const float2* q5 = (const float2*)g_k[4];
        const float2* q6 = (const float2*)g_k[5];
#pragma unroll
        for (int i = 0; i < 8; i++) {
          size_t off = (pxg0 + px0c + i) * 32 + (f0c >> 1);
          float klo, khi;
          upk2(klo, khi, accB[i]);
          out2[off] = make_float2(klo, khi);        // store k7 for FSAL reuse
          float2 v1 = q1[off], v3 = q3[off], v4 = q4[off], v5 = q5[off], v6 = q6[off];
          float2 a = y2[off], bb = yt2[off];        // yt holds y5
#define ECOMP(c, kacc) { \
          float e = hs * (E1f*v1.c + E3f*v3.c + E4f*v4.c + E5f*v5.c + E6f*v6.c + E7f*(kacc)); \
          float sc = 1e-3f + 1e-3f * fmaxf(fabsf(a.c), fabsf(bb.c)); \
          float rr = e / sc; local += (double)rr * (double)rr; }
          ECOMP(x, klo) ECOMP(y, khi)
#undef ECOMP
        }
      }
      setflag(g_f2, blk, ev);
    }
  }

  if (mode == 1) {
    __syncthreads();
    s_red[tid] = local;
    __syncthreads();
    for (int o = 256; o > 0; o >>= 1) {
      if (tid < o) s_red[tid] += s_red[tid + o];
      __syncthreads();
    }
    if (tid == 0) atomicAdd(&g_sumsq[it], s_red[0]);
  }
}

// ---------------- output head: 1x1, 64 -> 10 ----------------
__device__ void head_phase(const float* __restrict__ y, const float* __restrict__ wo,
                           const float* __restrict__ bo, float* __restrict__ out,
                           float* s, unsigned int nb) {
  float* w_s = s;        // [64][10]
  float* b_s = s + 640;
  int tid = threadIdx.x;
  __syncthreads();
  for (int i = tid; i < 640; i += NTHR) w_s[i] = wo[i];
  if (tid < 10) b_s[tid] = bo[tid];
  __syncthreads();
  for (int p = blockIdx.x * NTHR + tid; p < PXTOT; p += nb * NTHR) {
    const float4* yp = (const float4*)(y + (size_t)p * 64);
    float o[10];
#pragma unroll
    for (int k = 0; k < 10; k++) o[k] = b_s[k];
#pragma unroll 4
    for (int c4 = 0; c4 < 16; c4++) {
      float4 v = yp[c4];
      int c = c4 * 4;
#pragma unroll
      for (int k = 0; k < 10; k++)
        o[k] += v.x * w_s[c*10+k] + v.y * w_s[(c+1)*10+k] +
                v.z * w_s[(c+2)*10+k] + v.w * w_s[(c+3)*10+k];
    }
#pragma unroll
    for (int k = 0; k < 10; k++) out[(size_t)p * 10 + k] = o[k];
  }
}

// ---------------- the persistent ODE kernel ----------------
__global__ void __launch_bounds__(NTHR, 1)
ode_k(const float* __restrict__ x,
      const float* __restrict__ w1, const float* __restrict__ b1,
      const float* __restrict__ w2, const float* __restrict__ b2,
      const float* __restrict__ w3, const float* __restrict__ b3,
      const float* __restrict__ wo, const float* __restrict__ bo,
      float* __restrict__ out) {
  extern __shared__ float s_mem[];
  __shared__ double s_red[NTHR];
  __shared__ int s_t;
  const unsigned int nb = gridDim.x;
  unsigned int bt = 0;
  unsigned int ev = 0;

  const float A21 = (float)(1.0/5.0);
  const float A31 = (float)(3.0/40.0),  A32 = (float)(9.0/40.0);
  const float A41 = (float)(44.0/45.0), A42 = (float)(-56.0/15.0), A43 = (float)(32.0/9.0);
  const float A51 = (float)(19372.0/6561.0), A52 = (float)(-25360.0/2187.0),
              A53 = (float)(64448.0/6561.0), A54 = (float)(-212.0/729.0);
  const float A61 = (float)(9017.0/3168.0), A62 = (float)(-355.0/33.0),
              A63 = (float)(46732.0/5247.0), A64 = (float)(49.0/176.0),
              A65 = (float)(-5103.0/18656.0);
  const float Bc1 = (float)(35.0/384.0), Bc3 = (float)(500.0/1113.0),
              Bc4 = (float)(125.0/192.0), Bc5 = (float)(-2187.0/6784.0),
              Bc6 = (float)(11.0/84.0);

  // y0 = x
  {
    float4* d = (float4*)g_buf0;
    const float4* sx = (const float4*)x;
    for (int i = blockIdx.x * NTHR + threadIdx.x; i < NV4; i += nb * NTHR) d[i] = sx[i];
  }
  gsync(bt, nb);

  float t = 0.0f, h = 0.1f;
  int cur = 0;
  int ik1 = 0, ik7 = 6;      // FSAL buffer indices for k1 / k7

  for (int it = 0; it < NITERS; it++) {
    if (t >= 1.0f) break;       // uniform across all blocks (replicated controller)
    float* y  = cur ? g_buf1 : g_buf0;
    float* yt = cur ? g_buf0 : g_buf1;
    const float hs = fminf(h, 1.0f - t);
    const float t2 = t + hs * 0.2f;
    const float t3 = t + hs * 0.3f;
    const float t4 = t + hs * 0.8f;
    const float t5 = t + hs * (8.0f / 9.0f);
    const float t6 = t + hs;

#define FEVAL(SRC, KC, CC, DC, TV, KO, MODE, P0, P1, P2, P3, C0, C1, C2, C3, NL, CACC) \
    do {                                                                        \
      ev++;                                                                     \
      feval_phase((TV), (SRC), (KC), (CC), (DC), w1, b1, w2, b2, w3, b3,        \
                  (KO), (MODE), (P0), (P1), (P2), (P3),                         \
                  (C0), (C1), (C2), (C3), (NL), (CACC), y, yt, hs, it,          \
                  s_mem, s_red, ev, nb, &s_t);                                  \
    } while (0)

    // stage 1 (it==0 only): computes k1; epilogue yt unused (stage 2 inlines)
    if (it == 0) {
      FEVAL(y, y, 0.f, 0, t, ik1, 0, g_k[0], g_k[0], g_k[0], g_k[0],
            0,0,0,0, 0, A21);
    }
    // stage 2: conv1 inlines yt = y + hs*(A21*k1)  (FSAL)
    FEVAL(y, g_k[ik1], A21, 1, t2, 1, 0, g_k[ik1], g_k[0], g_k[0], g_k[0],
          A31,0,0,0, 1, A32);
    FEVAL(yt, y, 0.f, 0, t3, 2, 0, g_k[ik1], g_k[1], g_k[0], g_k[0],
          A41,A42,0,0, 2, A43);
    FEVAL(yt, y, 0.f, 0, t4, 3, 0, g_k[ik1], g_k[1], g_k[2], g_k[0],
          A51,A52,A53,0, 3, A54);
    FEVAL(yt, y, 0.f, 0, t5, 4, 0, g_k[ik1], g_k[1], g_k[2], g_k[3],
          A61,A62,A63,A64, 4, A65);
    FEVAL(yt, y, 0.f, 0, t6, 5, 0, g_k[ik1], g_k[2], g_k[3], g_k[4],
          Bc1,Bc3,Bc4,Bc5, 4, Bc6);                      // -> y5
    // stage 7 (err): stores k7 for FSAL; P0 carries k1 buffer for the E1 term
    FEVAL(yt, y, 0.f, 0, t6, ik7, 1, g_k[ik1], g_k[0], g_k[0], g_k[0],
          0,0,0,0, 0, 0.f);
#undef FEVAL

    gsync(bt, nb);

    // replicated controller
    double ss = g_sumsq[it];
    float en = sqrtf((float)(ss / (double)NY));
    int accept = (en <= 1.0f) ? 1 : 0;
    float ens = fmaxf(en, 1e-8f);
    float fac = fminf(fmaxf(0.9f * powf(ens, -0.2f), 0.2f), 10.0f);
    if (accept) {
      t = t + hs; cur ^= 1;
      int tmp = ik1; ik1 = ik7; ik7 = tmp;   // FSAL: k1 <- k7
    }
    h = fmaxf(hs * fac, 1e-4f);
  }

  const float* yfin = cur ? g_buf1 : g_buf0;
  head_phase(yfin, wo, bo, out, s_mem, nb);
}

// ---------------- launch: 2 graph nodes total ----------------
extern "C" void kernel_launch(void* const* d_in, const int* in_sizes, int n_in,
                              void* d_out, int out_size) {
  (void)in_sizes; (void)n_in; (void)out_size;
  const float* x  = (const float*)d_in[0];
  const float* w1 = (const float*)d_in[1];
  const float* b1 = (const float*)d_in[2];
  const float* w2 = (const float*)d_in[3];
  const float* b2 = (const float*)d_in[4];
  const float* w3 = (const float*)d_in[5];
  const float* b3 = (const float*)d_in[6];
  const float* wo = (const float*)d_in[7];
  const float* bo = (const float*)d_in[8];

  int dev = 0;
  cudaGetDevice(&dev);
  int nsm = 148;
  cudaDeviceGetAttribute(&nsm, cudaDevAttrMultiProcessorCount, dev);

  const int smem_bytes = S_TOT * 4;   // 215808 B
  cudaFuncSetAttribute(ode_k, cudaFuncAttributeMaxDynamicSharedMemorySize, smem_bytes);

  init_k<<<1, 1>>>();
  ode_k<<<nsm, NTHR, smem_bytes>>>(x, w1, b1, w2, b2, w3, b3, wo, bo, (float*)d_out);
}

// round 16
// speedup vs baseline: 1.1588x; 1.1588x over previous
#include <cuda_runtime.h>
#include <math.h>

// ---------------- problem dims ----------------
#define PXTOT 32768            // B*H*W = 8*64*64
#define NY    2097152          // PXTOT * 64
#define NH    4194304          // PXTOT * 128
#define NV4   (NY/4)
#define NITERS 32
#define NTHR  512
#define NPHASE 224             // max evals = 1 + 32*6 = 193

// ---------------- device state ----------------
__device__ float g_buf0[NY];       // y / ytmp ping-pong
__device__ float g_buf1[NY];
__device__ float g_k[7][NY];
__device__ float g_h1[NH];
__device__ double g_sumsq[NITERS];
__device__ unsigned int g_bar;
__device__ unsigned int g_tks[NPHASE];  // per-phase ticket counters
__device__ unsigned int g_f1[256];   // conv1 tile completion (eval number)
__device__ unsigned int g_f2[256];   // conv23 tile completion (eval number)

// ---------------- smem layout (floats) ----------------
// resident (loaded once): wt [9][128], w3 [129][64]
#define R_WT  0                // 1152
#define R_W3  1152             // 8256
#define DYN   9408
// conv23 dynamic: in bufs 2x[4][8][68]=2176ea, w2 bufs 2x[9][8][128]=9216ea, h2 [128][136]
#define C_IN0 (DYN)            // 2176
#define C_IN1 (DYN + 2176)     // 2176
#define C_W20 (DYN + 4352)     // 9216
#define C_W21 (DYN + 13568)    // 9216
#define C_H2  (DYN + 22784)    // 17408  -> end 49600
// conv1 dynamic: in bufs 2x[32][132]=4224ea, w bufs 2x[32][128]=4096ea
#define A_IN0 (DYN)
#define A_IN1 (DYN + 4224)
#define A_W0  (DYN + 8448)
#define A_W1  (DYN + 12544)    // end 16640
#define S_TOT 49600            // * 4 B = 198400 B

// ---------------- f32x2 helpers ----------------
__device__ __forceinline__ unsigned long long pk2(float lo, float hi) {
  unsigned long long r;
  asm("mov.b64 %0, {%1, %2};" : "=l"(r) : "f"(lo), "f"(hi));
  return r;
}
__device__ __forceinline__ unsigned long long dup2(float a) { return pk2(a, a); }
__device__ __forceinline__ unsigned long long fma2(unsigned long long a,
                                                   unsigned long long b,
                                                   unsigned long long c) {
  unsigned long long d;
  asm("fma.rn.f32x2 %0, %1, %2, %3;" : "=l"(d) : "l"(a), "l"(b), "l"(c));
  return d;
}
__device__ __forceinline__ void upk2(float& lo, float& hi, unsigned long long v) {
  asm("mov.b64 {%0, %1}, %2;" : "=f"(lo), "=f"(hi) : "l"(v));
}
// ---------------- cp.async helpers ----------------
__device__ __forceinline__ void cp16(float* smem_dst, const float4* gsrc) {
  unsigned int d = (unsigned int)__cvta_generic_to_shared(smem_dst);
  asm volatile("cp.async.cg.shared.global [%0], [%1], 16;" :: "r"(d), "l"(gsrc)
               : "memory");
}
__device__ __forceinline__ void cp_commit() {
  asm volatile("cp.async.commit_group;" ::: "memory");
}
__device__ __forceinline__ void cp_wait0() {
  asm volatile("cp.async.wait_group 0;" ::: "memory");
}

// ---------------- init node ----------------
__global__ void init_k() {
  g_bar = 0u;
  for (int i = 0; i < NPHASE; i++) g_tks[i] = 0u;
  for (int i = 0; i < NITERS; i++) g_sumsq[i] = 0.0;
  for (int i = 0; i < 256; i++) { g_f1[i] = 0u; g_f2[i] = 0u; }
}

// ---------------- software grid barrier ----------------
__device__ __forceinline__ void gsync(unsigned int& bt, unsigned int nb) {
  __syncthreads();
  if (threadIdx.x == 0) {
    __threadfence();
    atomicAdd(&g_bar, 1u);
    bt += nb;
    while ((int)(*(volatile unsigned int*)&g_bar - bt) < 0) __nanosleep(32);
    __threadfence();
  }
  __syncthreads();
}

// ---------------- per-phase tile tickets ----------------
__device__ __forceinline__ int grab(unsigned int* ctr, int nt, int* s_t) {
  if (threadIdx.x == 0) {
    unsigned int tk = atomicAdd(ctr, 1u);
    int loc = (int)tk;
    *s_t = (loc >= 0 && loc < nt) ? loc : -1;
  }
  __syncthreads();
  int r = *s_t;
  __syncthreads();
  return r;
}

// ---------------- dataflow flags ----------------
__device__ __forceinline__ void waitflags(unsigned int* f, int b, int plo, int phi,
                                          unsigned int thr) {
  if (threadIdx.x == 0) {
    for (int q = plo; q <= phi; q++) {
      volatile unsigned int* p = f + b * 32 + q;
      while (*p < thr) __nanosleep(20);
    }
    __threadfence();
  }
  __syncthreads();
}
__device__ __forceinline__ void setflag(unsigned int* f, int idx, unsigned int v) {
  __syncthreads();
  if (threadIdx.x == 0) {
    __threadfence();
    *(volatile unsigned int*)(f + idx) = v;
  }
}

// ---------------- fused f-eval: one ticket stream, flag-synced ----------------
// tickets 0..255: conv1 tiles (128 px = 2 rows), 256..511: conv23 tiles (same idx).
__device__ void feval_phase(
    float tval,
    const float* __restrict__ in,                     // conv1 source
    const float* __restrict__ kcmb, float ccmb, int do_cmb,  // inline FSAL combine
    const float* __restrict__ w1, const float* __restrict__ b1,
    const float* __restrict__ w2, const float* __restrict__ b2,
    const float* __restrict__ w3, const float* __restrict__ b3,
    int kout, int mode,
    const float* kl0, const float* kl1, const float* kl2, const float* kl3,
    float cl0, float cl1, float cl2, float cl3, int nload, float cacc,
    const float* __restrict__ y, float* __restrict__ yt,
    float hs, int it,
    float* s, double* s_red, unsigned int ev,
    unsigned int nb, int* s_t) {
  const int tid = threadIdx.x;
  const float4* w14 = (const float4*)w1;
  const float4* w24 = (const float4*)w2;
  const float4* in4c1 = (const float4*)in;
  const float4* kc4 = (const float4*)kcmb;
  const float4* h14 = (const float4*)g_h1;
  const float2* y2  = (const float2*)y;
  float2* yt2 = (float2*)yt;
  const float2* p0 = (const float2*)kl0;
  const float2* p1 = (const float2*)kl1;
  const float2* p2 = (const float2*)kl2;
  const float2* p3 = (const float2*)kl3;
  const unsigned long long td = dup2(tval);
  double local = 0.0;

  while (true) {
    int tk = grab(&g_tks[ev], 512, s_t);
    if (tk < 0) break;

    if (tk < 256) {
      // ================= conv1 tile (2-chunk pipelined) =================
      const int j = tk, jb = j >> 5, jp = j & 31;
      waitflags(g_f2, jb, jp > 0 ? jp - 1 : 0, jp < 31 ? jp + 1 : 31, ev - 1);
      const int f0  = (tid & 31) * 4;
      const int px0 = (tid >> 5) * 8;
      const int pxbase = j * 128;
      const int pxa = tid >> 3, c4a = tid & 7;          // in-stage indices (l=0)
      const int pxb = (tid + NTHR) >> 3, c4b = tid & 7; // l=1
      const int ka = tid >> 5, f4a = tid & 31;          // w-stage (l=0)
      const int kb = (tid + NTHR) >> 5;                 // l=1

      unsigned long long acc[8][2];
      {
        unsigned long long bp0 = pk2(b1[f0]   + tval * w1[f0],
                                     b1[f0+1] + tval * w1[f0+1]);
        unsigned long long bp1 = pk2(b1[f0+2] + tval * w1[f0+2],
                                     b1[f0+3] + tval * w1[f0+3]);
#pragma unroll
        for (int i = 0; i < 8; i++) { acc[i][0] = bp0; acc[i][1] = bp1; }
      }
      // helper lambdas (inlined by compiler)
      auto ld_in = [&](int ch, int px, int c4) -> float4 {
        size_t goff = (size_t)(pxbase + px) * 16 + (ch >> 2) + c4;
        float4 v = in4c1[goff];
        if (do_cmb) {
          float4 kv = kc4[goff];
          v.x = fmaf(hs, ccmb * kv.x, v.x);
          v.y = fmaf(hs, ccmb * kv.y, v.y);
          v.z = fmaf(hs, ccmb * kv.z, v.z);
          v.w = fmaf(hs, ccmb * kv.w, v.w);
        }
        return v;
      };
      auto st_in = [&](float* in_s, int px, int c4, float4 v) {
        in_s[(c4*4+0)*132 + px] = v.x; in_s[(c4*4+1)*132 + px] = v.y;
        in_s[(c4*4+2)*132 + px] = v.z; in_s[(c4*4+3)*132 + px] = v.w;
      };
      // stage chunk 0 (in: LDG+STS; w: cp.async)
      {
        float* in_s = s + A_IN0;
        st_in(in_s, pxa, c4a, ld_in(0, pxa, c4a));
        st_in(in_s, pxb, c4b, ld_in(0, pxb, c4b));
        cp16(&s[A_W0 + (ka*128 + f4a*4)], &w14[(size_t)(1 + ka) * 32 + f4a]);
        cp16(&s[A_W0 + (kb*128 + f4a*4)], &w14[(size_t)(1 + kb) * 32 + f4a]);
        cp_commit();
        cp_wait0();
      }
      __syncthreads();
      // prefetch chunk 1
      float4 pinA = ld_in(32, pxa, c4a);
      float4 pinB = ld_in(32, pxb, c4b);
      cp16(&s[A_W1 + (ka*128 + f4a*4)], &w14[(size_t)(1 + 32 + ka) * 32 + f4a]);
      cp16(&s[A_W1 + (kb*128 + f4a*4)], &w14[(size_t)(1 + 32 + kb) * 32 + f4a]);
      cp_commit();
#pragma unroll
      for (int c = 0; c < 2; c++) {
        const float* in_s = s + (c ? A_IN1 : A_IN0);
        const float* w_s  = s + (c ? A_W1  : A_W0);
#pragma unroll 4
        for (int k = 0; k < 32; k++) {
          ulonglong2 wA = *(const ulonglong2*)&w_s[k*128 + f0];
          float4 a0 = *(const float4*)&in_s[k*132 + px0];
          float4 a1 = *(const float4*)&in_s[k*132 + px0 + 4];
          const float* ap = (const float*)&a0;
#pragma unroll
          for (int i = 0; i < 4; i++) {
            unsigned long long a = dup2(ap[i]);
            acc[i][0] = fma2(a, wA.x, acc[i][0]);
            acc[i][1] = fma2(a, wA.y, acc[i][1]);
          }
          const float* ap1 = (const float*)&a1;
#pragma unroll
          for (int i = 0; i < 4; i++) {
            unsigned long long a = dup2(ap1[i]);
            acc[4+i][0] = fma2(a, wA.x, acc[4+i][0]);
            acc[4+i][1] = fma2(a, wA.y, acc[4+i][1]);
          }
        }
        if (c == 0) {
          float* in_s1 = s + A_IN1;
          st_in(in_s1, pxa, c4a, pinA);
          st_in(in_s1, pxb, c4b, pinB);
          cp_wait0();
          __syncthreads();
        }
      }
      float4* out4 = (float4*)g_h1;
#pragma unroll
      for (int i = 0; i < 8; i++) {
        float o[4];
        upk2(o[0], o[1], acc[i][0]); upk2(o[2], o[3], acc[i][1]);
#pragma unroll
        for (int jj = 0; jj < 4; jj++) o[jj] = fmaxf(o[jj], 0.f);
        out4[(size_t)(pxbase + px0 + i) * 32 + (f0 >> 2)] =
            make_float4(o[0], o[1], o[2], o[3]);
      }
      setflag(g_f1, j, ev);

    } else {
      // ================= conv23 tile (16-chunk pipelined) =================
      const int blk = tk - 256;
      const int b   = blk >> 5;
      const int p   = blk & 31;
      const int oy0 = p * 2;
      waitflags(g_f1, b, p > 0 ? p - 1 : 0, p < 31 ? p + 1 : 31, ev);
      const int f0   = (tid & 31) * 4;
      const int px0  = (tid >> 5) * 4;
      const int f0c  = (tid & 31) * 2;
      const int px0c = (tid >> 5) * 8;
      // staging indices: in = 1 float4/thread, w2 = up to 5 cp.async/thread
      const int ric = tid >> 7, remc = tid & 127, pxc = remc >> 1, qc = remc & 1;
      const int rowc = oy0 + ric - 1;
      const int rowok = (rowc >= 0 && rowc < 64);
      const size_t in_goff = ((size_t)((b * 64 + rowc) * 64 + pxc)) * 32;

      // halo zeros (both buffers) — threads 384..511
      if (tid >= 384) {
        int z = tid - 384;
        int bf = z >> 6, rem = z & 63;
        int ri = rem >> 4, cc = (rem >> 1) & 7, col = (rem & 1) * 65;
        s[(bf ? C_IN1 : C_IN0) + (ri * 8 + cc) * 68 + col] = 0.f;
      }
      unsigned long long acc[2][4][2];
      {
        unsigned long long bp0 = pk2(b2[f0], b2[f0+1]);
        unsigned long long bp1 = pk2(b2[f0+2], b2[f0+3]);
#pragma unroll
        for (int r = 0; r < 2; r++)
#pragma unroll
          for (int i = 0; i < 4; i++) { acc[r][i][0] = bp0; acc[r][i][1] = bp1; }
      }
      // ---- stage chunk 0 ----
      {
        float4 v = make_float4(0.f, 0.f, 0.f, 0.f);
        if (rowok) v = h14[in_goff + qc];
        float* bp = &s[C_IN0 + (ric * 8 + qc * 4) * 68 + pxc + 1];
        bp[0] = v.x; bp[68] = v.y; bp[136] = v.z; bp[204] = v.w;
#pragma unroll
        for (int l = 0; l < 5; l++) {
          int idx = tid + l * NTHR;
          if (idx < 2304) {
            int tap = idx / 256, rem = idx & 255, cc = rem >> 5, f4 = rem & 31;
            cp16(&s[C_W20 + ((tap * 8 + cc) * 128 + f4 * 4)],
                 &w24[((size_t)tap * 129 + 1 + cc) * 32 + f4]);
          }
        }
        cp_commit();
      }
      // time-channel contribution (resident wt) — hides chunk-0 staging latency
#pragma unroll
      for (int ky = 0; ky < 3; ky++) {
#pragma unroll
        for (int kx = 0; kx < 3; kx++) {
          ulonglong2 wp = *(const ulonglong2*)&s[R_WT + (ky * 3 + kx) * 128 + f0];
#pragma unroll
          for (int r = 0; r < 2; r++) {
            int grow = oy0 + r + ky - 1;
            if (grow >= 0 && grow < 64) {
#pragma unroll
              for (int i = 0; i < 4; i++) {
                int col = px0 + i + kx - 1;
                if (col >= 0 && col < 64) {
                  acc[r][i][0] = fma2(td, wp.x, acc[r][i][0]);
                  acc[r][i][1] = fma2(td, wp.y, acc[r][i][1]);
                }
              }
            }
          }
        }
      }
      cp_wait0();
      __syncthreads();
      // ---- pipelined chunk loop: 16 chunks x 8 channels ----
      for (int c = 0; c < 16; c++) {
        const int cur = c & 1;
        float4 pin;
        if (c < 15) {
          const int chn = (c + 1) * 8;
          pin = make_float4(0.f, 0.f, 0.f, 0.f);
          if (rowok) pin = h14[in_goff + (chn >> 2) + qc];
#pragma unroll
          for (int l = 0; l < 5; l++) {
            int idx = tid + l * NTHR;
            if (idx < 2304) {
              int tap = idx / 256, rem = idx & 255, cc = rem >> 5, f4 = rem & 31;
              cp16(&s[(cur ? C_W20 : C_W21) + ((tap * 8 + cc) * 128 + f4 * 4)],
                   &w24[((size_t)tap * 129 + 1 + chn + cc) * 32 + f4]);
            }
          }
          cp_commit();
        }
        // compute chunk c
        const float* in_s = s + (cur ? C_IN1 : C_IN0);
        const float* w_s  = s + (cur ? C_W21 : C_W20);
        for (int cc = 0; cc < 8; cc++) {
          unsigned long long dv[4][6];
#pragma unroll
          for (int ri = 0; ri < 4; ri++) {
            const float* bp = &in_s[(ri * 8 + cc) * 68 + px0];
            float4 a = *(const float4*)bp;
            float2 t2 = *(const float2*)(bp + 4);
            dv[ri][0] = dup2(a.x); dv[ri][1] = dup2(a.y);
            dv[ri][2] = dup2(a.z); dv[ri][3] = dup2(a.w);
            dv[ri][4] = dup2(t2.x); dv[ri][5] = dup2(t2.y);
          }
#pragma unroll
          for (int ky = 0; ky < 3; ky++) {
#pragma unroll
            for (int kx = 0; kx < 3; kx++) {
              ulonglong2 wv =
                  *(const ulonglong2*)&w_s[((ky * 3 + kx) * 8 + cc) * 128 + f0];
#pragma unroll
              for (int r = 0; r < 2; r++) {
#pragma unroll
                for (int i = 0; i < 4; i++) {
                  unsigned long long a = dv[r + ky][i + kx];
                  acc[r][i][0] = fma2(a, wv.x, acc[r][i][0]);
                  acc[r][i][1] = fma2(a, wv.y, acc[r][i][1]);
                }
              }
            }
          }
        }
        if (c < 15) {
          float* bp = &s[(cur ? C_IN0 : C_IN1) + (ric * 8 + qc * 4) * 68 + pxc + 1];
          bp[0] = pin.x; bp[68] = pin.y; bp[136] = pin.z; bp[204] = pin.w;
          cp_wait0();
        }
        __syncthreads();
      }
      // stage A epilogue: relu + h2 tile to smem [px][136]
#pragma unroll
      for (int r = 0; r < 2; r++) {
#pragma unroll
        for (int i = 0; i < 4; i++) {
          int p_t = r * 64 + px0 + i;
#pragma unroll
          for (int jj = 0; jj < 2; jj++) {
            float lo, hi;
            upk2(lo, hi, acc[r][i][jj]);
            *(float2*)&s[C_H2 + p_t * 136 + f0 + 2*jj] =
                make_float2(fmaxf(lo, 0.f), fmaxf(hi, 0.f));
          }
        }
      }
      __syncthreads();
      // stage B: conv3 on the smem tile (resident w3)
      unsigned long long accB[8];
      {
        unsigned long long bp = pk2(b3[f0c]   + tval * w3[f0c],
                                    b3[f0c+1] + tval * w3[f0c+1]);
#pragma unroll
        for (int i = 0; i < 8; i++) accB[i] = bp;
      }
#pragma unroll 2
      for (int k0 = 0; k0 < 128; k0 += 4) {
        float4 av[8];
#pragma unroll
        for (int i = 0; i < 8; i++)
          av[i] = *(const float4*)&s[C_H2 + (px0c + i) * 136 + k0];
#pragma unroll
        for (int kk = 0; kk < 4; kk++) {
          unsigned long long wv =
              *(const unsigned long long*)&s[R_W3 + (1 + k0 + kk) * 64 + f0c];
#pragma unroll
          for (int i = 0; i < 8; i++)
            accB[i] = fma2(dup2(((const float*)&av[i])[kk]), wv, accB[i]);
        }
      }
      // fused dopri5 epilogue (float2 granularity)
      const size_t pxg0 = (size_t)(b * 64 + oy0) * 64;
      float2* out2 = (float2*)&g_k[kout][0];
      if (mode == 0) {
#pragma unroll
        for (int i = 0; i < 8; i++) {
          size_t off = (pxg0 + px0c + i) * 32 + (f0c >> 1);
          float klo, khi;
          upk2(klo, khi, accB[i]);
          out2[off] = make_float2(klo, khi);
          float sx = 0.f, sy = 0.f;
          if (nload > 0) { float2 v = p0[off]; sx = fmaf(cl0,v.x,sx); sy = fmaf(cl0,v.y,sy); }
          if (nload > 1) { float2 v = p1[off]; sx = fmaf(cl1,v.x,sx); sy = fmaf(cl1,v.y,sy); }
          if (nload > 2) { float2 v = p2[off]; sx = fmaf(cl2,v.x,sx); sy = fmaf(cl2,v.y,sy); }
          if (nload > 3) { float2 v = p3[off]; sx = fmaf(cl3,v.x,sx); sy = fmaf(cl3,v.y,sy); }
          sx = fmaf(cacc, klo, sx); sy = fmaf(cacc, khi, sy);
          float2 yv = y2[off];
          yt2[off] = make_float2(fmaf(hs,sx,yv.x), fmaf(hs,sy,yv.y));
        }
      } else {
        const float E1f = (float)( 71.0 / 57600.0);
        const float E3f = (float)(-71.0 / 16695.0);
        const float E4f = (float)( 71.0 / 1920.0);
        const float E5f = (float)(-17253.0 / 339200.0);
        const float E6f = (float)( 22.0 / 525.0);
        const float E7f = (float)(-1.0 / 40.0);
        const float2* q1 = p0;                      // k1 buffer (FSAL-indexed)
        const float2* q3 = (const float2*)g_k[2];
        const float2* q4 = (const float2*)g_k[3];
        const float2* q5 = (const float2*)g_k[4];
        const float2* q6 = (const float2*)g_k[5];
#pragma unroll
        for (int i = 0; i < 8; i++) {
          size_t off = (pxg0 + px0c + i) * 32 + (f0c >> 1);
          float klo, khi;
          upk2(klo, khi, accB[i]);
          out2[off] = make_float2(klo, khi);        // store k7 for FSAL reuse
          float2 v1 = q1[off], v3 = q3[off], v4 = q4[off], v5 = q5[off], v6 = q6[off];
          float2 a = y2[off], bb = yt2[off];        // yt holds y5
#define ECOMP(c, kacc) { \
          float e = hs * (E1f*v1.c + E3f*v3.c + E4f*v4.c + E5f*v5.c + E6f*v6.c + E7f*(kacc)); \
          float sc = 1e-3f + 1e-3f * fmaxf(fabsf(a.c), fabsf(bb.c)); \
          float rr = e / sc; local += (double)rr * (double)rr; }
          ECOMP(x, klo) ECOMP(y, khi)
#undef ECOMP
        }
      }
      setflag(g_f2, blk, ev);
    }
  }

  if (mode == 1) {
    __syncthreads();
    s_red[tid] = local;
    __syncthreads();
    for (int o = 256; o > 0; o >>= 1) {
      if (tid < o) s_red[tid] += s_red[tid + o];
      __syncthreads();
    }
    if (tid == 0) atomicAdd(&g_sumsq[it], s_red[0]);
  }
}

// ---------------- output head: 1x1, 64 -> 10 ----------------
__device__ void head_phase(const float* __restrict__ y, const float* __restrict__ wo,
                           const float* __restrict__ bo, float* __restrict__ out,
                           float* s, unsigned int nb) {
  float* w_s = s + DYN;  // [64][10]
  float* b_s = w_s + 640;
  int tid = threadIdx.x;
  __syncthreads();
  for (int i = tid; i < 640; i += NTHR) w_s[i] = wo[i];
  if (tid < 10) b_s[tid] = bo[tid];
  __syncthreads();
  for (int p = blockIdx.x * NTHR + tid; p < PXTOT; p += nb * NTHR) {
    const float4* yp = (const float4*)(y + (size_t)p * 64);
    float o[10];
#pragma unroll
    for (int k = 0; k < 10; k++) o[k] = b_s[k];
#pragma unroll 4
    for (int c4 = 0; c4 < 16; c4++) {
      float4 v = yp[c4];
      int c = c4 * 4;
#pragma unroll
      for (int k = 0; k < 10; k++)
        o[k] += v.x * w_s[c*10+k] + v.y * w_s[(c+1)*10+k] +
                v.z * w_s[(c+2)*10+k] + v.w * w_s[(c+3)*10+k];
    }
#pragma unroll
    for (int k = 0; k < 10; k++) out[(size_t)p * 10 + k] = o[k];
  }
}

// ---------------- the persistent ODE kernel ----------------
__global__ void __launch_bounds__(NTHR, 1)
ode_k(const float* __restrict__ x,
      const float* __restrict__ w1, const float* __restrict__ b1,
      const float* __restrict__ w2, const float* __restrict__ b2,
      const float* __restrict__ w3, const float* __restrict__ b3,
      const float* __restrict__ wo, const float* __restrict__ bo,
      float* __restrict__ out) {
  extern __shared__ float s_mem[];
  __shared__ double s_red[NTHR];
  __shared__ int s_t;
  const unsigned int nb = gridDim.x;
  unsigned int bt = 0;
  unsigned int ev = 0;
  const int tid = threadIdx.x;

  const float A21 = (float)(1.0/5.0);
  const float A31 = (float)(3.0/40.0),  A32 = (float)(9.0/40.0);
  const float A41 = (float)(44.0/45.0), A42 = (float)(-56.0/15.0), A43 = (float)(32.0/9.0);
  const float A51 = (float)(19372.0/6561.0), A52 = (float)(-25360.0/2187.0),
              A53 = (float)(64448.0/6561.0), A54 = (float)(-212.0/729.0);
  const float A61 = (float)(9017.0/3168.0), A62 = (float)(-355.0/33.0),
              A63 = (float)(46732.0/5247.0), A64 = (float)(49.0/176.0),
              A65 = (float)(-5103.0/18656.0);
  const float Bc1 = (float)(35.0/384.0), Bc3 = (float)(500.0/1113.0),
              Bc4 = (float)(125.0/192.0), Bc5 = (float)(-2187.0/6784.0),
              Bc6 = (float)(11.0/84.0);

  // resident smem: wt (time row of each tap) + w3
  {
    const float4* w24 = (const float4*)w2;
    const float4* w34 = (const float4*)w3;
    if (tid < 288) {
      int tap = tid >> 5, f4 = tid & 31;
      ((float4*)(s_mem + R_WT))[tap * 32 + f4] = w24[(size_t)tap * 129 * 32 + f4];
    }
#pragma unroll
    for (int l = 0; l < 5; l++) {
      int idx = tid + l * NTHR;
      if (idx < 2064) ((float4*)(s_mem + R_W3))[idx] = w34[idx];
    }
  }
  // y0 = x
  {
    float4* d = (float4*)g_buf0;
    const float4* sx = (const float4*)x;
    for (int i = blockIdx.x * NTHR + tid; i < NV4; i += nb * NTHR) d[i] = sx[i];
  }
  gsync(bt, nb);

  float t = 0.0f, h = 0.1f;
  int cur = 0;
  int ik1 = 0, ik7 = 6;      // FSAL buffer indices for k1 / k7

  for (int it = 0; it < NITERS; it++) {
    if (t >= 1.0f) break;       // uniform across all blocks (replicated controller)
    float* y  = cur ? g_buf1 : g_buf0;
    float* yt = cur ? g_buf0 : g_buf1;
    const float hs = fminf(h, 1.0f - t);
    const float t2 = t + hs * 0.2f;
    const float t3 = t + hs * 0.3f;
    const float t4 = t + hs * 0.8f;
    const float t5 = t + hs * (8.0f / 9.0f);
    const float t6 = t + hs;

#define FEVAL(SRC, KC, CC, DC, TV, KO, MODE, P0, P1, P2, P3, C0, C1, C2, C3, NL, CACC) \
    do {                                                                        \
      ev++;                                                                     \
      feval_phase((TV), (SRC), (KC), (CC), (DC), w1, b1, w2, b2, w3, b3,        \
                  (KO), (MODE), (P0), (P1), (P2), (P3),                         \
                  (C0), (C1), (C2), (C3), (NL), (CACC), y, yt, hs, it,          \
                  s_mem, s_red, ev, nb, &s_t);                                  \
    } while (0)

    // stage 1 (it==0 only): computes k1; epilogue yt unused (stage 2 inlines)
    if (it == 0) {
      FEVAL(y, y, 0.f, 0, t, ik1, 0, g_k[0], g_k[0], g_k[0], g_k[0],
            0,0,0,0, 0, A21);
    }
    // stage 2: conv1 inlines yt = y + hs*(A21*k1)  (FSAL)
    FEVAL(y, g_k[ik1], A21, 1, t2, 1, 0, g_k[ik1], g_k[0], g_k[0], g_k[0],
          A31,0,0,0, 1, A32);
    FEVAL(yt, y, 0.f, 0, t3, 2, 0, g_k[ik1], g_k[1], g_k[0], g_k[0],
          A41,A42,0,0, 2, A43);
    FEVAL(yt, y, 0.f, 0, t4, 3, 0, g_k[ik1], g_k[1], g_k[2], g_k[0],
          A51,A52,A53,0, 3, A54);
    FEVAL(yt, y, 0.f, 0, t5, 4, 0, g_k[ik1], g_k[1], g_k[2], g_k[3],
          A61,A62,A63,A64, 4, A65);
    FEVAL(yt, y, 0.f, 0, t6, 5, 0, g_k[ik1], g_k[2], g_k[3], g_k[4],
          Bc1,Bc3,Bc4,Bc5, 4, Bc6);                      // -> y5
    // stage 7 (err): stores k7 for FSAL; P0 carries k1 buffer for the E1 term
    FEVAL(yt, y, 0.f, 0, t6, ik7, 1, g_k[ik1], g_k[0], g_k[0], g_k[0],
          0,0,0,0, 0, 0.f);
#undef FEVAL

    gsync(bt, nb);

    // replicated controller
    double ss = g_sumsq[it];
    float en = sqrtf((float)(ss / (double)NY));
    int accept = (en <= 1.0f) ? 1 : 0;
    float ens = fmaxf(en, 1e-8f);
    float fac = fminf(fmaxf(0.9f * powf(ens, -0.2f), 0.2f), 10.0f);
    if (accept) {
      t = t + hs; cur ^= 1;
      int tmp = ik1; ik1 = ik7; ik7 = tmp;   // FSAL: k1 <- k7
    }
    h = fmaxf(hs * fac, 1e-4f);
  }

  const float* yfin = cur ? g_buf1 : g_buf0;
  head_phase(yfin, wo, bo, out, s_mem, nb);
}

// ---------------- launch: 2 graph nodes total ----------------
extern "C" void kernel_launch(void* const* d_in, const int* in_sizes, int n_in,
                              void* d_out, int out_size) {
  (void)in_sizes; (void)n_in; (void)out_size;
  const float* x  = (const float*)d_in[0];
  const float* w1 = (const float*)d_in[1];
  const float* b1 = (const float*)d_in[2];
  const float* w2 = (const float*)d_in[3];
  const float* b2 = (const float*)d_in[4];
  const float* w3 = (const float*)d_in[5];
  const float* b3 = (const float*)d_in[6];
  const float* wo = (const float*)d_in[7];
  const float* bo = (const float*)d_in[8];

  int dev = 0;
  cudaGetDevice(&dev);
  int nsm = 148;
  cudaDeviceGetAttribute(&nsm, cudaDevAttrMultiProcessorCount, dev);

  const int smem_bytes = S_TOT * 4;   // 198400 B
  cudaFuncSetAttribute(ode_k, cudaFuncAttributeMaxDynamicSharedMemorySize, smem_bytes);

  init_k<<<1, 1>>>();
  ode_k<<<nsm, NTHR, smem_bytes>>>(x, w1, b1, w2, b2, w3, b3, wo, bo, (float*)d_out);
}